// round 4
// baseline (speedup 1.0000x reference)
#include <cuda_runtime.h>
#include <cuda_bf16.h>
#include <cstdint>

#define EDIM 256
#define NCODES 1024
#define TILE_M 128
#define MAXROWS 131072
#define MARGIN_Q 48                // 0.75 * quant scale 64
#define GAP2_THRESH 0.01           // fp64 gap below which we emulate ref fp32 order

// ---------------- device scratch (no allocs allowed) ----------------
__device__ __align__(16) __nv_bfloat16 g_emb_bf16[NCODES * EDIM];
__device__ __align__(16) unsigned g_top[MAXROWS * 16];
__device__ double g_partials[MAXROWS / 8];

// ---------------- helpers ----------------
__device__ __forceinline__ uint32_t smem_u32(const void* p) {
    uint32_t a;
    asm("{ .reg .u64 t; cvta.to.shared.u64 t, %1; cvt.u32.u64 %0, t; }" : "=r"(a) : "l"(p));
    return a;
}
__device__ __forceinline__ void cp_async16(uint32_t dst, const void* src) {
    asm volatile("cp.async.cg.shared.global [%0], [%1], 16;" :: "r"(dst), "l"(src) : "memory");
}
#define CP_COMMIT() asm volatile("cp.async.commit_group;" ::: "memory")
#define CP_WAIT0()  asm volatile("cp.async.wait_group 0;" ::: "memory")
#define CP_WAIT1()  asm volatile("cp.async.wait_group 1;" ::: "memory")

__device__ __forceinline__ void ldsm4(uint32_t& r0, uint32_t& r1, uint32_t& r2, uint32_t& r3,
                                      uint32_t addr) {
    asm volatile("ldmatrix.sync.aligned.m8n8.x4.shared.b16 {%0,%1,%2,%3}, [%4];"
                 : "=r"(r0), "=r"(r1), "=r"(r2), "=r"(r3) : "r"(addr));
}
__device__ __forceinline__ void mma16816(float* c, uint32_t a0, uint32_t a1, uint32_t a2,
                                         uint32_t a3, uint32_t b0, uint32_t b1) {
    asm volatile("mma.sync.aligned.m16n8k16.row.col.f32.bf16.bf16.f32 "
                 "{%0,%1,%2,%3}, {%4,%5,%6,%7}, {%8,%9}, {%0,%1,%2,%3};"
                 : "+f"(c[0]), "+f"(c[1]), "+f"(c[2]), "+f"(c[3])
                 : "r"(a0), "r"(a1), "r"(a2), "r"(a3), "r"(b0), "r"(b1));
}

#define TOP4_INS(v0, v1, v2, v3, key) do {            \
    unsigned _t0 = min(v0, key); v0 = max(v0, key);   \
    unsigned _t1 = min(v1, _t0); v1 = max(v1, _t0);   \
    unsigned _t2 = min(v2, _t1); v2 = max(v2, _t1);   \
    v3 = max(v3, _t2);                                \
} while (0)

#define SMEM_A 0
#define SMEM_B 65536
#define SMEM_TOTAL 131072

// ---------------- kernel 1: emb f32 -> bf16 ----------------
__global__ void conv_emb_kernel(const float* __restrict__ emb) {
    int i = blockIdx.x * 256 + threadIdx.x;
    float4 v = ((const float4*)emb)[i];
    __nv_bfloat162 lo = __float22bfloat162_rn(make_float2(v.x, v.y));
    __nv_bfloat162 hi = __float22bfloat162_rn(make_float2(v.z, v.w));
    ((__nv_bfloat162*)g_emb_bf16)[i * 2]     = lo;
    ((__nv_bfloat162*)g_emb_bf16)[i * 2 + 1] = hi;
}

// ---------------- kernel 2: HMMA GEMM + fused top-4 ----------------
__device__ __forceinline__ void issue_b_chunk(uint32_t sbase, int buf, int nt, int tid) {
    #pragma unroll
    for (int i = 0; i < 8; i++) {
        int id = tid + i * 256;
        int row = id >> 5, c = id & 31;
        uint32_t dst = sbase + SMEM_B + (uint32_t)buf * 32768u +
                       (uint32_t)row * 512u + (uint32_t)((c ^ (row & 7)) << 4);
        cp_async16(dst, g_emb_bf16 + (((size_t)nt * 64 + row) << 8) + (c << 3));
    }
    CP_COMMIT();
}

__global__ void __launch_bounds__(256, 1) vq_main_kernel(const float* __restrict__ z) {
    extern __shared__ __align__(1024) uint8_t smem[];
    uint32_t sbase = smem_u32(smem);
    int tid = threadIdx.x;
    int w = tid >> 5, lane = tid & 31;
    int m0 = blockIdx.x * TILE_M;

    issue_b_chunk(sbase, 0, 0, tid);
    issue_b_chunk(sbase, 1, 1, tid);

    {
        const float4* z4 = (const float4*)(z + (size_t)m0 * EDIM);
        #pragma unroll
        for (int i = 0; i < 16; i++) {
            int id = tid + i * 256;
            int row = id >> 5, c = id & 31;
            float4 va = z4[(size_t)row * 64 + c * 2];
            float4 vb = z4[(size_t)row * 64 + c * 2 + 1];
            __nv_bfloat162 p0 = __float22bfloat162_rn(make_float2(va.x, va.y));
            __nv_bfloat162 p1 = __float22bfloat162_rn(make_float2(va.z, va.w));
            __nv_bfloat162 p2 = __float22bfloat162_rn(make_float2(vb.x, vb.y));
            __nv_bfloat162 p3 = __float22bfloat162_rn(make_float2(vb.z, vb.w));
            uint32_t off = (uint32_t)row * 512u + (uint32_t)((c ^ (row & 7)) << 4);
            *(uint4*)(smem + SMEM_A + off) =
                make_uint4(*(uint32_t*)&p0, *(uint32_t*)&p1, *(uint32_t*)&p2, *(uint32_t*)&p3);
        }
    }

    int arow  = w * 16 + (lane & 15);
    uint32_t abase = sbase + SMEM_A + (uint32_t)arow * 512u;
    int aswz = arow & 7;
    int ahalf = lane >> 4;
    int brow_off = ((lane >> 4) << 3) + (lane & 7);
    int bhalf = (lane >> 3) & 1;
    int bswz = lane & 7;

    int tg = lane & 3;
    unsigned v0 = 0, v1 = 0, v2 = 0, v3 = 0;
    unsigned u0 = 0, u1 = 0, u2 = 0, u3 = 0;

    __syncthreads();

    for (int t = 0; t < 16; t++) {
        if (t < 15) { CP_WAIT1(); } else { CP_WAIT0(); }
        __syncthreads();

        uint32_t bb = sbase + SMEM_B + (uint32_t)(t & 1) * 32768u;
        float acc[8][4];
        #pragma unroll
        for (int s = 0; s < 8; s++)
            acc[s][0] = acc[s][1] = acc[s][2] = acc[s][3] = 0.f;

        #pragma unroll
        for (int k = 0; k < 16; k++) {
            int ca = k * 2 + ahalf;
            uint32_t a0, a1, a2, a3;
            ldsm4(a0, a1, a2, a3, abase + (uint32_t)((ca ^ aswz) << 4));
            int cb = k * 2 + bhalf;
            #pragma unroll
            for (int p = 0; p < 4; p++) {
                int brow = p * 16 + brow_off;
                uint32_t b0, b1, b2, b3;
                ldsm4(b0, b1, b2, b3,
                      bb + (uint32_t)brow * 512u + (uint32_t)((cb ^ bswz) << 4));
                mma16816(acc[2 * p],     a0, a1, a2, a3, b0, b1);
                mma16816(acc[2 * p + 1], a0, a1, a2, a3, b2, b3);
            }
        }

        __syncthreads();
        if (t + 2 < 16) issue_b_chunk(sbase, t & 1, t + 2, tid);

        unsigned cbase = (unsigned)(t * 64 + tg * 2);
        #pragma unroll
        for (int s = 0; s < 8; s++) {
            unsigned c0 = cbase + s * 8;
            unsigned k0 = (((unsigned)fmaf(acc[s][0], 64.f, 16384.f)) << 16) | c0;
            unsigned k1 = (((unsigned)fmaf(acc[s][1], 64.f, 16384.f)) << 16) | (c0 + 1);
            unsigned k2 = (((unsigned)fmaf(acc[s][2], 64.f, 16384.f)) << 16) | c0;
            unsigned k3 = (((unsigned)fmaf(acc[s][3], 64.f, 16384.f)) << 16) | (c0 + 1);
            TOP4_INS(v0, v1, v2, v3, k0);
            TOP4_INS(v0, v1, v2, v3, k1);
            TOP4_INS(u0, u1, u2, u3, k2);
            TOP4_INS(u0, u1, u2, u3, k3);
        }
    }

    int row0 = m0 + w * 16 + (lane >> 2);
    ((uint4*)g_top)[(size_t)row0 * 4 + tg]       = make_uint4(v0, v1, v2, v3);
    ((uint4*)g_top)[(size_t)(row0 + 8) * 4 + tg] = make_uint4(u0, u1, u2, u3);
}

// ---------------- kernel 3: finalize (3-stage exact argmax, gather, loss) ----------------
__global__ void __launch_bounds__(256) vq_finalize_kernel(
        const float* __restrict__ z, const float* __restrict__ emb,
        float* __restrict__ out, int nrows) {
    __shared__ double wacc[8];
    int w = threadIdx.x >> 5, lane = threadIdx.x & 31;
    int r = blockIdx.x * 8 + w;

    unsigned k = (lane < 16) ? g_top[(size_t)r * 16 + lane] : 0u;
    unsigned m = k, s2 = 0;
    #pragma unroll
    for (int off = 16; off; off >>= 1) {
        unsigned om = __shfl_xor_sync(0xFFFFFFFFu, m, off);
        unsigned os = __shfl_xor_sync(0xFFFFFFFFu, s2, off);
        s2 = max(max(s2, os), min(m, om));
        m = max(m, om);
    }
    int best = (int)(m & 0xFFFFu);

    if (((m >> 16) - (s2 >> 16)) < (unsigned)MARGIN_Q) {
        // ---- stage 2: fp64 rescore of flagged candidates ----
        unsigned thr = (m >> 16);
        thr = (thr > (unsigned)MARGIN_Q) ? thr - (unsigned)MARGIN_Q : 0u;
        bool flag = (lane < 16) && ((k >> 16) >= thr);
        unsigned mask = __ballot_sync(0xFFFFFFFFu, flag);
        unsigned mask_sv = mask;
        float z8[8];
        {
            const float4* zr = (const float4*)(z + (size_t)r * EDIM + lane * 8);
            float4 a0 = zr[0], a1 = zr[1];
            z8[0] = a0.x; z8[1] = a0.y; z8[2] = a0.z; z8[3] = a0.w;
            z8[4] = a1.x; z8[5] = a1.y; z8[6] = a1.z; z8[7] = a1.w;
        }
        double bd = -1e300, bd2 = -1e300; int bi = 0x7FFFFFFF;
        while (mask) {
            int b = __ffs(mask) - 1; mask &= mask - 1;
            unsigned ck = __shfl_sync(0xFFFFFFFFu, k, b);
            int ci = (int)(ck & 0xFFFFu);
            const float* er = emb + (size_t)ci * EDIM + lane * 8;
            double s = 0.0;
            #pragma unroll
            for (int j = 0; j < 8; j++) s += (double)z8[j] * (double)er[j];
            #pragma unroll
            for (int off = 16; off; off >>= 1) s += __shfl_xor_sync(0xFFFFFFFFu, s, off);
            if (s > bd) { bd2 = bd; bd = s; bi = ci; }
            else if (s > bd2) bd2 = s;
        }
        best = bi;

        if (bd - bd2 < GAP2_THRESH) {
            // ---- stage 3: emulate reference fp32 (sequential fmaf chain over k) ----
            bool f3 = (mask_sv >> lane) & 1u;       // implies lane < 16
            int ci = (int)(k & 0xFFFFu);
            float sc = -3.4e38f;
            if (f3) {
                const float* zr = z + (size_t)r * EDIM;
                const float* er = emb + (size_t)ci * EDIM;
                float c = 0.f;
                for (int j = 0; j < EDIM; j++) c = fmaf(zr[j], er[j], c);
                sc = c;
            }
            int ii = f3 ? ci : 0x7FFFFFFF;
            #pragma unroll
            for (int off = 16; off; off >>= 1) {
                float osc = __shfl_xor_sync(0xFFFFFFFFu, sc, off);
                int   oii = __shfl_xor_sync(0xFFFFFFFFu, ii, off);
                if (osc > sc || (osc == sc && oii < ii)) { sc = osc; ii = oii; }
            }
            best = ii;
        }
    }

    // gather + straight-through output (mirror ref rounding) + loss partial
    const float4* z4 = (const float4*)(z + (size_t)r * EDIM);
    const float4* e4 = (const float4*)(emb + (size_t)best * EDIM);
    float4* o4 = (float4*)(out + (size_t)r * EDIM);
    float acc = 0.f;
    #pragma unroll
    for (int c = 0; c < 2; c++) {
        int i = lane + c * 32;
        float4 zz = z4[i], ee = e4[i], oo;
        float d0 = ee.x - zz.x, d1 = ee.y - zz.y, d2 = ee.z - zz.z, d3 = ee.w - zz.w;
        oo.x = zz.x + d0; oo.y = zz.y + d1; oo.z = zz.z + d2; oo.w = zz.w + d3;
        o4[i] = oo;
        acc += d0 * d0 + d1 * d1 + d2 * d2 + d3 * d3;
    }
    #pragma unroll
    for (int off = 16; off; off >>= 1) acc += __shfl_xor_sync(0xFFFFFFFFu, acc, off);
    if (lane == 0) {
        wacc[w] = (double)acc;
        out[(size_t)nrows * EDIM + 2 + r] = (float)best;
    }
    __syncthreads();
    if (threadIdx.x == 0) {
        double t = 0.0;
        #pragma unroll
        for (int i = 0; i < 8; i++) t += wacc[i];
        g_partials[blockIdx.x] = t;
    }
}

// ---------------- kernel 4: deterministic loss reduce ----------------
__global__ void vq_reduce_kernel(float* __restrict__ out, int nparts,
                                 double inv_nelem, size_t zq) {
    __shared__ double sm[256];
    int tid = threadIdx.x;
    double s = 0.0;
    for (int i = tid; i < nparts; i += 256) s += g_partials[i];
    sm[tid] = s;
    __syncthreads();
    for (int off = 128; off; off >>= 1) {
        if (tid < off) sm[tid] += sm[tid + off];
        __syncthreads();
    }
    if (tid == 0) {
        double mse = sm[0] * inv_nelem;
        out[zq]     = (float)mse;
        out[zq + 1] = (float)(0.25 * mse);
    }
}

// ---------------- launch ----------------
extern "C" void kernel_launch(void* const* d_in, const int* in_sizes, int n_in,
                              void* d_out, int out_size) {
    const float* z   = (const float*)d_in[0];
    const float* emb = (const float*)d_in[1];
    float* out = (float*)d_out;
    int nrows = in_sizes[0] / EDIM;              // 131072

    cudaFuncSetAttribute(vq_main_kernel,
                         cudaFuncAttributeMaxDynamicSharedMemorySize, SMEM_TOTAL);

    conv_emb_kernel<<<in_sizes[1] / 4 / 256, 256>>>(emb);
    vq_main_kernel<<<nrows / TILE_M, 256, SMEM_TOTAL>>>(z);
    vq_finalize_kernel<<<nrows / 8, 256>>>(z, emb, out, nrows);
    vq_reduce_kernel<<<1, 256>>>(out, nrows / 8,
                                 1.0 / ((double)nrows * EDIM),
                                 (size_t)nrows * EDIM);
}

// round 5
// speedup vs baseline: 1.1877x; 1.1877x over previous
#include <cuda_runtime.h>
#include <cuda_bf16.h>
#include <cstdint>

#define EDIM 256
#define NCODES 1024
#define TILE_M 128
#define MAXROWS 131072
#define KEY_BIAS 1024.0f
#define MARGIN_F 1.0f              // rescue margin (0.75 + quantization slack)
#define GAP2_THRESH 0.01           // fp64 gap below which we emulate ref fp32 order

// ---------------- device scratch (no allocs allowed) ----------------
__device__ __align__(16) __nv_bfloat16 g_emb_bf16[NCODES * EDIM];
__device__ __align__(16) unsigned g_top[MAXROWS * 32];
__device__ double g_partials[MAXROWS / 8];

// ---------------- helpers ----------------
__device__ __forceinline__ uint32_t smem_u32(const void* p) {
    uint32_t a;
    asm("{ .reg .u64 t; cvta.to.shared.u64 t, %1; cvt.u32.u64 %0, t; }" : "=r"(a) : "l"(p));
    return a;
}
__device__ __forceinline__ void cp_async16(uint32_t dst, const void* src) {
    asm volatile("cp.async.cg.shared.global [%0], [%1], 16;" :: "r"(dst), "l"(src) : "memory");
}
#define CP_COMMIT() asm volatile("cp.async.commit_group;" ::: "memory")
#define CP_WAIT0()  asm volatile("cp.async.wait_group 0;" ::: "memory")
#define CP_WAIT1()  asm volatile("cp.async.wait_group 1;" ::: "memory")

__device__ __forceinline__ void ldsm4(uint32_t& r0, uint32_t& r1, uint32_t& r2, uint32_t& r3,
                                      uint32_t addr) {
    asm volatile("ldmatrix.sync.aligned.m8n8.x4.shared.b16 {%0,%1,%2,%3}, [%4];"
                 : "=r"(r0), "=r"(r1), "=r"(r2), "=r"(r3) : "r"(addr));
}
__device__ __forceinline__ void mma16816(float* c, uint32_t a0, uint32_t a1, uint32_t a2,
                                         uint32_t a3, uint32_t b0, uint32_t b1) {
    asm volatile("mma.sync.aligned.m16n8k16.row.col.f32.bf16.bf16.f32 "
                 "{%0,%1,%2,%3}, {%4,%5,%6,%7}, {%8,%9}, {%0,%1,%2,%3};"
                 : "+f"(c[0]), "+f"(c[1]), "+f"(c[2]), "+f"(c[3])
                 : "r"(a0), "r"(a1), "r"(a2), "r"(a3), "r"(b0), "r"(b1));
}

// top-2 insert (descending): 3 ops
#define TOP2_INS(v0, v1, key) do {                    \
    unsigned _t0 = min(v0, key); v0 = max(v0, key);   \
    v1 = max(v1, _t0);                                \
} while (0)

// integer-comparable key: monotonic float bits (positive range), 10-bit code id
__device__ __forceinline__ unsigned make_key(float s, unsigned code) {
    return (__float_as_uint(s + KEY_BIAS) & 0xFFFFFC00u) | code;
}
__device__ __forceinline__ float key_score(unsigned k) {
    return __uint_as_float(k & 0xFFFFFC00u);   // biased score, quantized
}

// smem: A tile 128x256 bf16 (64KB) + B double buffer 2x(128 codes x 512B = 64KB)
#define SMEM_A 0
#define SMEM_B 65536
#define SMEM_TOTAL 196608

// ---------------- kernel 1: emb f32 -> bf16 ----------------
__global__ void conv_emb_kernel(const float* __restrict__ emb) {
    int i = blockIdx.x * 256 + threadIdx.x;
    float4 v = ((const float4*)emb)[i];
    __nv_bfloat162 lo = __float22bfloat162_rn(make_float2(v.x, v.y));
    __nv_bfloat162 hi = __float22bfloat162_rn(make_float2(v.z, v.w));
    ((__nv_bfloat162*)g_emb_bf16)[i * 2]     = lo;
    ((__nv_bfloat162*)g_emb_bf16)[i * 2 + 1] = hi;
}

// ---------------- kernel 2: HMMA GEMM + fused top-2/thread ----------------
// 16 warps = 4 row-groups (Mw=32) x 4 col-groups (32 codes of each 128-code chunk)
__device__ __forceinline__ void issue_b_chunk(uint32_t sbase, int buf, int nt, int tid) {
    // 128 codes x 512B = 4096 x 16B granules; 8 per thread (512 threads)
    #pragma unroll
    for (int i = 0; i < 8; i++) {
        int id = tid + i * 512;
        int row = id >> 5, c = id & 31;
        uint32_t dst = sbase + SMEM_B + (uint32_t)buf * 65536u +
                       (uint32_t)row * 512u + (uint32_t)((c ^ (row & 7)) << 4);
        cp_async16(dst, g_emb_bf16 + (((size_t)nt * 128 + row) << 8) + (c << 3));
    }
    CP_COMMIT();
}

__global__ void __launch_bounds__(512, 1) vq_main_kernel(const float* __restrict__ z) {
    extern __shared__ __align__(1024) uint8_t smem[];
    uint32_t sbase = smem_u32(smem);
    int tid = threadIdx.x;
    int w = tid >> 5, lane = tid & 31;
    int rg = w >> 2, cg = w & 3;
    int m0 = blockIdx.x * TILE_M;

    issue_b_chunk(sbase, 0, 0, tid);
    issue_b_chunk(sbase, 1, 1, tid);

    // A tile: 128 rows x 256 f32 -> bf16, swizzled (chunk c of row r at r*512 + ((c^(r&7))<<4))
    {
        const float4* z4 = (const float4*)(z + (size_t)m0 * EDIM);
        #pragma unroll
        for (int i = 0; i < 8; i++) {
            int id = tid + i * 512;
            int row = id >> 5, c = id & 31;
            float4 va = z4[(size_t)row * 64 + c * 2];
            float4 vb = z4[(size_t)row * 64 + c * 2 + 1];
            __nv_bfloat162 p0 = __float22bfloat162_rn(make_float2(va.x, va.y));
            __nv_bfloat162 p1 = __float22bfloat162_rn(make_float2(va.z, va.w));
            __nv_bfloat162 p2 = __float22bfloat162_rn(make_float2(vb.x, vb.y));
            __nv_bfloat162 p3 = __float22bfloat162_rn(make_float2(vb.z, vb.w));
            uint32_t off = (uint32_t)row * 512u + (uint32_t)((c ^ (row & 7)) << 4);
            *(uint4*)(smem + SMEM_A + off) =
                make_uint4(*(uint32_t*)&p0, *(uint32_t*)&p1, *(uint32_t*)&p2, *(uint32_t*)&p3);
        }
    }

    // per-lane ldmatrix addressing
    uint32_t abase0 = sbase + SMEM_A + (uint32_t)(rg * 32 + (lane & 15)) * 512u;
    uint32_t abase1 = abase0 + 16 * 512u;
    int aswz = lane & 7;
    int ahalf = lane >> 4;
    int brow_off = ((lane >> 4) << 3) + (lane & 7);   // 0..15 within 16-code group
    int bhalf = (lane >> 3) & 1;
    int bswz = lane & 7;

    // top-2 keys for 4 rows covered by this thread: [mt*2 + rh]
    unsigned t2a[4], t2b[4];
    #pragma unroll
    for (int i = 0; i < 4; i++) { t2a[i] = 0; t2b[i] = 0; }

    __syncthreads();   // A visible

    for (int t = 0; t < 8; t++) {
        if (t < 7) { CP_WAIT1(); } else { CP_WAIT0(); }
        __syncthreads();                               // B(t) visible to all

        uint32_t bb = sbase + SMEM_B + (uint32_t)(t & 1) * 65536u + (uint32_t)cg * 16384u;
        float acc0[4][4], acc1[4][4];                  // [n8 group s][frag], mt=0 / mt=1
        #pragma unroll
        for (int s = 0; s < 4; s++)
            #pragma unroll
            for (int i = 0; i < 4; i++) { acc0[s][i] = 0.f; acc1[s][i] = 0.f; }

        #pragma unroll
        for (int k = 0; k < 16; k++) {
            int ca = k * 2 + ahalf;
            uint32_t a0, a1, a2, a3, a4, a5, a6, a7;
            ldsm4(a0, a1, a2, a3, abase0 + (uint32_t)((ca ^ aswz) << 4));
            ldsm4(a4, a5, a6, a7, abase1 + (uint32_t)((ca ^ aswz) << 4));
            int cb = k * 2 + bhalf;
            #pragma unroll
            for (int p = 0; p < 2; p++) {
                int brow = p * 16 + brow_off;
                uint32_t b0, b1, b2, b3;
                ldsm4(b0, b1, b2, b3,
                      bb + (uint32_t)brow * 512u + (uint32_t)((cb ^ bswz) << 4));
                mma16816(acc0[2 * p],     a0, a1, a2, a3, b0, b1);
                mma16816(acc0[2 * p + 1], a0, a1, a2, a3, b2, b3);
                mma16816(acc1[2 * p],     a4, a5, a6, a7, b0, b1);
                mma16816(acc1[2 * p + 1], a4, a5, a6, a7, b2, b3);
            }
        }

        __syncthreads();                               // done reading B(t&1)
        if (t + 2 < 8) issue_b_chunk(sbase, t & 1, t + 2, tid);

        // fold into top-2 (keys: monotonic float bits | code)
        unsigned cb0 = (unsigned)(t * 128 + cg * 32 + (lane & 3) * 2);
        #pragma unroll
        for (int s = 0; s < 4; s++) {
            unsigned c0 = cb0 + s * 8;
            unsigned k00 = make_key(acc0[s][0], c0);
            unsigned k01 = make_key(acc0[s][1], c0 + 1);
            unsigned k02 = make_key(acc0[s][2], c0);
            unsigned k03 = make_key(acc0[s][3], c0 + 1);
            TOP2_INS(t2a[0], t2b[0], k00);
            TOP2_INS(t2a[0], t2b[0], k01);
            TOP2_INS(t2a[1], t2b[1], k02);
            TOP2_INS(t2a[1], t2b[1], k03);
            unsigned k10 = make_key(acc1[s][0], c0);
            unsigned k11 = make_key(acc1[s][1], c0 + 1);
            unsigned k12 = make_key(acc1[s][2], c0);
            unsigned k13 = make_key(acc1[s][3], c0 + 1);
            TOP2_INS(t2a[2], t2b[2], k10);
            TOP2_INS(t2a[2], t2b[2], k11);
            TOP2_INS(t2a[3], t2b[3], k12);
            TOP2_INS(t2a[3], t2b[3], k13);
        }
    }

    // store: 32 candidate slots per row = 16 uint2; slot = cg*4 + (lane&3)
    #pragma unroll
    for (int mt = 0; mt < 2; mt++)
        #pragma unroll
        for (int rh = 0; rh < 2; rh++) {
            int row = m0 + rg * 32 + mt * 16 + rh * 8 + (lane >> 2);
            ((uint2*)g_top)[(size_t)row * 16 + cg * 4 + (lane & 3)] =
                make_uint2(t2a[mt * 2 + rh], t2b[mt * 2 + rh]);
        }
}

// ---------------- kernel 3: finalize (3-stage exact argmax, gather, loss) ----------------
__global__ void __launch_bounds__(256) vq_finalize_kernel(
        const float* __restrict__ z, const float* __restrict__ emb,
        float* __restrict__ out, int nrows) {
    __shared__ double wacc[8];
    int w = threadIdx.x >> 5, lane = threadIdx.x & 31;
    int r = blockIdx.x * 8 + w;

    unsigned k = g_top[(size_t)r * 32 + lane];
    unsigned m = k, s2 = 0;
    #pragma unroll
    for (int off = 16; off; off >>= 1) {
        unsigned om = __shfl_xor_sync(0xFFFFFFFFu, m, off);
        unsigned os = __shfl_xor_sync(0xFFFFFFFFu, s2, off);
        s2 = max(max(s2, os), min(m, om));
        m = max(m, om);
    }
    int best = (int)(m & 1023u);

    float fm = key_score(m);
    if (fm - key_score(s2) < MARGIN_F) {
        // ---- stage 2: fp64 rescore of flagged candidates ----
        bool flag = key_score(k) >= fm - MARGIN_F;
        unsigned mask = __ballot_sync(0xFFFFFFFFu, flag);
        unsigned mask_sv = mask;
        float z8[8];
        {
            const float4* zr = (const float4*)(z + (size_t)r * EDIM + lane * 8);
            float4 a0 = zr[0], a1 = zr[1];
            z8[0] = a0.x; z8[1] = a0.y; z8[2] = a0.z; z8[3] = a0.w;
            z8[4] = a1.x; z8[5] = a1.y; z8[6] = a1.z; z8[7] = a1.w;
        }
        double bd = -1e300, bd2 = -1e300; int bi = 0x7FFFFFFF;
        while (mask) {
            int b = __ffs(mask) - 1; mask &= mask - 1;
            unsigned ck = __shfl_sync(0xFFFFFFFFu, k, b);
            int ci = (int)(ck & 1023u);
            const float* er = emb + (size_t)ci * EDIM + lane * 8;
            double s = 0.0;
            #pragma unroll
            for (int j = 0; j < 8; j++) s += (double)z8[j] * (double)er[j];
            #pragma unroll
            for (int off = 16; off; off >>= 1) s += __shfl_xor_sync(0xFFFFFFFFu, s, off);
            if (s > bd) { bd2 = bd; bd = s; bi = ci; }
            else if (s > bd2) bd2 = s;
        }
        best = bi;

        if (bd - bd2 < GAP2_THRESH) {
            // ---- stage 3: emulate reference fp32 (sequential fmaf chain over k) ----
            bool f3 = (mask_sv >> lane) & 1u;
            int ci = (int)(k & 1023u);
            float sc = -3.4e38f;
            if (f3) {
                const float* zr = z + (size_t)r * EDIM;
                const float* er = emb + (size_t)ci * EDIM;
                float c = 0.f;
                for (int j = 0; j < EDIM; j++) c = fmaf(zr[j], er[j], c);
                sc = c;
            }
            int ii = f3 ? ci : 0x7FFFFFFF;
            #pragma unroll
            for (int off = 16; off; off >>= 1) {
                float osc = __shfl_xor_sync(0xFFFFFFFFu, sc, off);
                int   oii = __shfl_xor_sync(0xFFFFFFFFu, ii, off);
                if (osc > sc || (osc == sc && oii < ii)) { sc = osc; ii = oii; }
            }
            best = ii;
        }
    }

    // gather + straight-through output (mirror ref rounding) + loss partial
    const float4* z4 = (const float4*)(z + (size_t)r * EDIM);
    const float4* e4 = (const float4*)(emb + (size_t)best * EDIM);
    float4* o4 = (float4*)(out + (size_t)r * EDIM);
    float acc = 0.f;
    #pragma unroll
    for (int c = 0; c < 2; c++) {
        int i = lane + c * 32;
        float4 zz = z4[i], ee = e4[i], oo;
        float d0 = ee.x - zz.x, d1 = ee.y - zz.y, d2 = ee.z - zz.z, d3 = ee.w - zz.w;
        oo.x = zz.x + d0; oo.y = zz.y + d1; oo.z = zz.z + d2; oo.w = zz.w + d3;
        o4[i] = oo;
        acc += d0 * d0 + d1 * d1 + d2 * d2 + d3 * d3;
    }
    #pragma unroll
    for (int off = 16; off; off >>= 1) acc += __shfl_xor_sync(0xFFFFFFFFu, acc, off);
    if (lane == 0) {
        wacc[w] = (double)acc;
        out[(size_t)nrows * EDIM + 2 + r] = (float)best;
    }
    __syncthreads();
    if (threadIdx.x == 0) {
        double t = 0.0;
        #pragma unroll
        for (int i = 0; i < 8; i++) t += wacc[i];
        g_partials[blockIdx.x] = t;
    }
}

// ---------------- kernel 4: deterministic loss reduce ----------------
__global__ void __launch_bounds__(512) vq_reduce_kernel(
        float* __restrict__ out, int nparts, double inv_nelem, size_t zq) {
    __shared__ double sm[512];
    int tid = threadIdx.x;
    double s = 0.0;
    #pragma unroll 4
    for (int i = tid; i < nparts; i += 512) s += g_partials[i];
    sm[tid] = s;
    __syncthreads();
    for (int off = 256; off; off >>= 1) {
        if (tid < off) sm[tid] += sm[tid + off];
        __syncthreads();
    }
    if (tid == 0) {
        double mse = sm[0] * inv_nelem;
        out[zq]     = (float)mse;
        out[zq + 1] = (float)(0.25 * mse);
    }
}

// ---------------- launch ----------------
extern "C" void kernel_launch(void* const* d_in, const int* in_sizes, int n_in,
                              void* d_out, int out_size) {
    const float* z   = (const float*)d_in[0];
    const float* emb = (const float*)d_in[1];
    float* out = (float*)d_out;
    int nrows = in_sizes[0] / EDIM;              // 131072

    cudaFuncSetAttribute(vq_main_kernel,
                         cudaFuncAttributeMaxDynamicSharedMemorySize, SMEM_TOTAL);

    conv_emb_kernel<<<in_sizes[1] / 4 / 256, 256>>>(emb);
    vq_main_kernel<<<nrows / TILE_M, 512, SMEM_TOTAL>>>(z);
    vq_finalize_kernel<<<nrows / 8, 256>>>(z, emb, out, nrows);
    vq_reduce_kernel<<<1, 512>>>(out, nrows / 8,
                                 1.0 / ((double)nrows * EDIM),
                                 (size_t)nrows * EDIM);
}

// round 6
// speedup vs baseline: 1.2481x; 1.0509x over previous
#include <cuda_runtime.h>
#include <cuda_fp16.h>
#include <cstdint>

#define EDIM 256
#define NCODES 1024
#define TILE_M 128
#define MAXROWS 131072
#define KEY_BIAS 1024.0f
#define MARGIN_F 0.75f             // rescue margin (>> 6*sigma_fp16 + key quant)
#define GAP2_THRESH 0.01           // fp64 gap below which we emulate ref fp32 order

// ---------------- device scratch (no allocs allowed) ----------------
__device__ __align__(16) __half g_emb_f16[NCODES * EDIM];
__device__ __align__(16) unsigned g_top[MAXROWS * 32];
__device__ double g_partials[MAXROWS / 8];
__device__ double g_partials2[64];

// ---------------- helpers ----------------
__device__ __forceinline__ uint32_t smem_u32(const void* p) {
    uint32_t a;
    asm("{ .reg .u64 t; cvta.to.shared.u64 t, %1; cvt.u32.u64 %0, t; }" : "=r"(a) : "l"(p));
    return a;
}
__device__ __forceinline__ void cp_async16(uint32_t dst, const void* src) {
    asm volatile("cp.async.cg.shared.global [%0], [%1], 16;" :: "r"(dst), "l"(src) : "memory");
}
#define CP_COMMIT() asm volatile("cp.async.commit_group;" ::: "memory")
#define CP_WAIT0()  asm volatile("cp.async.wait_group 0;" ::: "memory")
#define CP_WAIT1()  asm volatile("cp.async.wait_group 1;" ::: "memory")

__device__ __forceinline__ void ldsm4(uint32_t& r0, uint32_t& r1, uint32_t& r2, uint32_t& r3,
                                      uint32_t addr) {
    asm volatile("ldmatrix.sync.aligned.m8n8.x4.shared.b16 {%0,%1,%2,%3}, [%4];"
                 : "=r"(r0), "=r"(r1), "=r"(r2), "=r"(r3) : "r"(addr));
}
// fp16 accumulate HMMA: C frag = 2 regs (4 halves)
__device__ __forceinline__ void mma16816h(uint32_t* c, uint32_t a0, uint32_t a1, uint32_t a2,
                                          uint32_t a3, uint32_t b0, uint32_t b1) {
    asm volatile("mma.sync.aligned.m16n8k16.row.col.f16.f16.f16.f16 "
                 "{%0,%1}, {%2,%3,%4,%5}, {%6,%7}, {%0,%1};"
                 : "+r"(c[0]), "+r"(c[1])
                 : "r"(a0), "r"(a1), "r"(a2), "r"(a3), "r"(b0), "r"(b1));
}

// top-2 insert (descending): 3 ops
#define TOP2_INS(v0, v1, key) do {                    \
    unsigned _t0 = min(v0, key); v0 = max(v0, key);   \
    v1 = max(v1, _t0);                                \
} while (0)

// integer-comparable key: monotonic float bits (positive range), 10-bit code id
__device__ __forceinline__ unsigned make_key(float s, unsigned code) {
    return (__float_as_uint(s + KEY_BIAS) & 0xFFFFFC00u) | code;
}
__device__ __forceinline__ float key_score(unsigned k) {
    return __uint_as_float(k & 0xFFFFFC00u);   // biased score, quantized (step 0.125)
}

// smem: A tile 128x256 f16 (64KB) + B double buffer 2x(128 codes x 512B = 64KB)
#define SMEM_A 0
#define SMEM_B 65536
#define SMEM_TOTAL 196608

// ---------------- kernel 1: emb f32 -> f16 ----------------
__global__ void conv_emb_kernel(const float* __restrict__ emb) {
    int i = blockIdx.x * 256 + threadIdx.x;
    float4 v = ((const float4*)emb)[i];
    __half2 lo = __float22half2_rn(make_float2(v.x, v.y));
    __half2 hi = __float22half2_rn(make_float2(v.z, v.w));
    ((__half2*)g_emb_f16)[i * 2]     = lo;
    ((__half2*)g_emb_f16)[i * 2 + 1] = hi;
}

// ---------------- kernel 2: HMMA(f16 acc) GEMM + fused top-2/thread ----------------
// 16 warps = 4 row-groups (Mw=32) x 4 col-groups (32 codes of each 128-code chunk)
__device__ __forceinline__ void issue_b_chunk(uint32_t sbase, int buf, int nt, int tid) {
    // 128 codes x 512B = 4096 x 16B granules; 8 per thread (512 threads)
    #pragma unroll
    for (int i = 0; i < 8; i++) {
        int id = tid + i * 512;
        int row = id >> 5, c = id & 31;
        uint32_t dst = sbase + SMEM_B + (uint32_t)buf * 65536u +
                       (uint32_t)row * 512u + (uint32_t)((c ^ (row & 7)) << 4);
        cp_async16(dst, g_emb_f16 + (((size_t)nt * 128 + row) << 8) + (c << 3));
    }
    CP_COMMIT();
}

__global__ void __launch_bounds__(512, 1) vq_main_kernel(const float* __restrict__ z) {
    extern __shared__ __align__(1024) uint8_t smem[];
    uint32_t sbase = smem_u32(smem);
    int tid = threadIdx.x;
    int w = tid >> 5, lane = tid & 31;
    int rg = w >> 2, cg = w & 3;
    int m0 = blockIdx.x * TILE_M;

    issue_b_chunk(sbase, 0, 0, tid);
    issue_b_chunk(sbase, 1, 1, tid);

    // A tile: 128 rows x 256 f32 -> f16, swizzled (granule c of row r at r*512 + ((c^(r&7))<<4))
    {
        const float4* z4 = (const float4*)(z + (size_t)m0 * EDIM);
        #pragma unroll
        for (int i = 0; i < 8; i++) {
            int id = tid + i * 512;
            int row = id >> 5, c = id & 31;
            float4 va = z4[(size_t)row * 64 + c * 2];
            float4 vb = z4[(size_t)row * 64 + c * 2 + 1];
            __half2 p0 = __float22half2_rn(make_float2(va.x, va.y));
            __half2 p1 = __float22half2_rn(make_float2(va.z, va.w));
            __half2 p2 = __float22half2_rn(make_float2(vb.x, vb.y));
            __half2 p3 = __float22half2_rn(make_float2(vb.z, vb.w));
            uint32_t off = (uint32_t)row * 512u + (uint32_t)((c ^ (row & 7)) << 4);
            *(uint4*)(smem + SMEM_A + off) =
                make_uint4(*(uint32_t*)&p0, *(uint32_t*)&p1, *(uint32_t*)&p2, *(uint32_t*)&p3);
        }
    }

    // per-lane ldmatrix addressing
    uint32_t abase0 = sbase + SMEM_A + (uint32_t)(rg * 32 + (lane & 15)) * 512u;
    uint32_t abase1 = abase0 + 16 * 512u;
    int aswz = lane & 7;
    int ahalf = lane >> 4;
    int brow_off = ((lane >> 4) << 3) + (lane & 7);   // 0..15 within 16-code group
    int bhalf = (lane >> 3) & 1;
    int bswz = lane & 7;

    // top-2 keys for 4 rows covered by this thread: [mt*2 + rh]
    unsigned t2a[4], t2b[4];
    #pragma unroll
    for (int i = 0; i < 4; i++) { t2a[i] = 0; t2b[i] = 0; }

    __syncthreads();   // A visible

    for (int t = 0; t < 8; t++) {
        if (t < 7) { CP_WAIT1(); } else { CP_WAIT0(); }
        __syncthreads();                               // B(t) visible to all

        uint32_t bb = sbase + SMEM_B + (uint32_t)(t & 1) * 65536u + (uint32_t)cg * 16384u;
        uint32_t acc0[4][2], acc1[4][2];               // f16x2 accums: [n8 group][row half]
        #pragma unroll
        for (int s = 0; s < 4; s++) {
            acc0[s][0] = 0u; acc0[s][1] = 0u;
            acc1[s][0] = 0u; acc1[s][1] = 0u;
        }

        #pragma unroll
        for (int k = 0; k < 16; k++) {
            int ca = k * 2 + ahalf;
            uint32_t a0, a1, a2, a3, a4, a5, a6, a7;
            ldsm4(a0, a1, a2, a3, abase0 + (uint32_t)((ca ^ aswz) << 4));
            ldsm4(a4, a5, a6, a7, abase1 + (uint32_t)((ca ^ aswz) << 4));
            int cb = k * 2 + bhalf;
            #pragma unroll
            for (int p = 0; p < 2; p++) {
                int brow = p * 16 + brow_off;
                uint32_t b0, b1, b2, b3;
                ldsm4(b0, b1, b2, b3,
                      bb + (uint32_t)brow * 512u + (uint32_t)((cb ^ bswz) << 4));
                mma16816h(acc0[2 * p],     a0, a1, a2, a3, b0, b1);
                mma16816h(acc0[2 * p + 1], a0, a1, a2, a3, b2, b3);
                mma16816h(acc1[2 * p],     a4, a5, a6, a7, b0, b1);
                mma16816h(acc1[2 * p + 1], a4, a5, a6, a7, b2, b3);
            }
        }

        __syncthreads();                               // done reading B(t&1)
        if (t + 2 < 8) issue_b_chunk(sbase, t & 1, t + 2, tid);

        // fold into top-2 (keys: monotonic float bits | code)
        unsigned cb0 = (unsigned)(t * 128 + cg * 32 + (lane & 3) * 2);
        #pragma unroll
        for (int s = 0; s < 4; s++) {
            unsigned c0 = cb0 + s * 8;
            float2 f00 = __half22float2(*(__half2*)&acc0[s][0]);  // row g,   cols c0,c0+1
            float2 f01 = __half22float2(*(__half2*)&acc0[s][1]);  // row g+8
            float2 f10 = __half22float2(*(__half2*)&acc1[s][0]);  // row g+16
            float2 f11 = __half22float2(*(__half2*)&acc1[s][1]);  // row g+24
            TOP2_INS(t2a[0], t2b[0], make_key(f00.x, c0));
            TOP2_INS(t2a[0], t2b[0], make_key(f00.y, c0 + 1));
            TOP2_INS(t2a[1], t2b[1], make_key(f01.x, c0));
            TOP2_INS(t2a[1], t2b[1], make_key(f01.y, c0 + 1));
            TOP2_INS(t2a[2], t2b[2], make_key(f10.x, c0));
            TOP2_INS(t2a[2], t2b[2], make_key(f10.y, c0 + 1));
            TOP2_INS(t2a[3], t2b[3], make_key(f11.x, c0));
            TOP2_INS(t2a[3], t2b[3], make_key(f11.y, c0 + 1));
        }
    }

    // store: 32 candidate slots per row = 16 uint2; slot = cg*4 + (lane&3)
    #pragma unroll
    for (int mt = 0; mt < 2; mt++)
        #pragma unroll
        for (int rh = 0; rh < 2; rh++) {
            int row = m0 + rg * 32 + mt * 16 + rh * 8 + (lane >> 2);
            ((uint2*)g_top)[(size_t)row * 16 + cg * 4 + (lane & 3)] =
                make_uint2(t2a[mt * 2 + rh], t2b[mt * 2 + rh]);
        }
}

// ---------------- kernel 3: finalize (3-stage exact argmax, gather, loss) ----------------
__global__ void __launch_bounds__(256) vq_finalize_kernel(
        const float* __restrict__ z, const float* __restrict__ emb,
        float* __restrict__ out, int nrows) {
    __shared__ double wacc[8];
    int w = threadIdx.x >> 5, lane = threadIdx.x & 31;
    int r = blockIdx.x * 8 + w;

    unsigned k = g_top[(size_t)r * 32 + lane];
    unsigned m = k, s2 = 0;
    #pragma unroll
    for (int off = 16; off; off >>= 1) {
        unsigned om = __shfl_xor_sync(0xFFFFFFFFu, m, off);
        unsigned os = __shfl_xor_sync(0xFFFFFFFFu, s2, off);
        s2 = max(max(s2, os), min(m, om));
        m = max(m, om);
    }
    int best = (int)(m & 1023u);

    float fm = key_score(m);
    if (fm - key_score(s2) < MARGIN_F) {
        // ---- stage 2: fp64 rescore of flagged candidates ----
        bool flag = key_score(k) >= fm - MARGIN_F;
        unsigned mask = __ballot_sync(0xFFFFFFFFu, flag);
        unsigned mask_sv = mask;
        float z8[8];
        {
            const float4* zr = (const float4*)(z + (size_t)r * EDIM + lane * 8);
            float4 a0 = zr[0], a1 = zr[1];
            z8[0] = a0.x; z8[1] = a0.y; z8[2] = a0.z; z8[3] = a0.w;
            z8[4] = a1.x; z8[5] = a1.y; z8[6] = a1.z; z8[7] = a1.w;
        }
        double bd = -1e300, bd2 = -1e300; int bi = 0x7FFFFFFF;
        while (mask) {
            int b = __ffs(mask) - 1; mask &= mask - 1;
            unsigned ck = __shfl_sync(0xFFFFFFFFu, k, b);
            int ci = (int)(ck & 1023u);
            const float* er = emb + (size_t)ci * EDIM + lane * 8;
            double s = 0.0;
            #pragma unroll
            for (int j = 0; j < 8; j++) s += (double)z8[j] * (double)er[j];
            #pragma unroll
            for (int off = 16; off; off >>= 1) s += __shfl_xor_sync(0xFFFFFFFFu, s, off);
            if (s > bd) { bd2 = bd; bd = s; bi = ci; }
            else if (s > bd2) bd2 = s;
        }
        best = bi;

        if (bd - bd2 < GAP2_THRESH) {
            // ---- stage 3: emulate reference fp32 (sequential fmaf chain over k) ----
            bool f3 = (mask_sv >> lane) & 1u;
            int ci = (int)(k & 1023u);
            float sc = -3.4e38f;
            if (f3) {
                const float* zr = z + (size_t)r * EDIM;
                const float* er = emb + (size_t)ci * EDIM;
                float c = 0.f;
                for (int j = 0; j < EDIM; j++) c = fmaf(zr[j], er[j], c);
                sc = c;
            }
            int ii = f3 ? ci : 0x7FFFFFFF;
            #pragma unroll
            for (int off = 16; off; off >>= 1) {
                float osc = __shfl_xor_sync(0xFFFFFFFFu, sc, off);
                int   oii = __shfl_xor_sync(0xFFFFFFFFu, ii, off);
                if (osc > sc || (osc == sc && oii < ii)) { sc = osc; ii = oii; }
            }
            best = ii;
        }
    }

    // gather + straight-through output (mirror ref rounding) + loss partial
    const float4* z4 = (const float4*)(z + (size_t)r * EDIM);
    const float4* e4 = (const float4*)(emb + (size_t)best * EDIM);
    float4* o4 = (float4*)(out + (size_t)r * EDIM);
    float acc = 0.f;
    #pragma unroll
    for (int c = 0; c < 2; c++) {
        int i = lane + c * 32;
        float4 zz = z4[i], ee = e4[i], oo;
        float d0 = ee.x - zz.x, d1 = ee.y - zz.y, d2 = ee.z - zz.z, d3 = ee.w - zz.w;
        oo.x = zz.x + d0; oo.y = zz.y + d1; oo.z = zz.z + d2; oo.w = zz.w + d3;
        o4[i] = oo;
        acc += d0 * d0 + d1 * d1 + d2 * d2 + d3 * d3;
    }
    #pragma unroll
    for (int off = 16; off; off >>= 1) acc += __shfl_xor_sync(0xFFFFFFFFu, acc, off);
    if (lane == 0) {
        wacc[w] = (double)acc;
        out[(size_t)nrows * EDIM + 2 + r] = (float)best;
    }
    __syncthreads();
    if (threadIdx.x == 0) {
        double t = 0.0;
        #pragma unroll
        for (int i = 0; i < 8; i++) t += wacc[i];
        g_partials[blockIdx.x] = t;
    }
}

// ---------------- kernels 4/5: two-stage deterministic loss reduce ----------------
__global__ void __launch_bounds__(256) vq_reduce1_kernel(int nparts) {
    __shared__ double sm[256];
    int tid = threadIdx.x;
    int base = blockIdx.x * (nparts / 64);
    double s = 0.0;
    for (int i = tid; i < nparts / 64; i += 256) s += g_partials[base + i];
    sm[tid] = s;
    __syncthreads();
    for (int off = 128; off; off >>= 1) {
        if (tid < off) sm[tid] += sm[tid + off];
        __syncthreads();
    }
    if (tid == 0) g_partials2[blockIdx.x] = sm[0];
}

__global__ void __launch_bounds__(64) vq_reduce2_kernel(
        float* __restrict__ out, double inv_nelem, size_t zq) {
    __shared__ double sm[64];
    int tid = threadIdx.x;
    sm[tid] = g_partials2[tid];
    __syncthreads();
    for (int off = 32; off; off >>= 1) {
        if (tid < off) sm[tid] += sm[tid + off];
        __syncthreads();
    }
    if (tid == 0) {
        double mse = sm[0] * inv_nelem;
        out[zq]     = (float)mse;
        out[zq + 1] = (float)(0.25 * mse);
    }
}

// ---------------- launch ----------------
extern "C" void kernel_launch(void* const* d_in, const int* in_sizes, int n_in,
                              void* d_out, int out_size) {
    const float* z   = (const float*)d_in[0];
    const float* emb = (const float*)d_in[1];
    float* out = (float*)d_out;
    int nrows = in_sizes[0] / EDIM;              // 131072

    cudaFuncSetAttribute(vq_main_kernel,
                         cudaFuncAttributeMaxDynamicSharedMemorySize, SMEM_TOTAL);

    conv_emb_kernel<<<in_sizes[1] / 4 / 256, 256>>>(emb);
    vq_main_kernel<<<nrows / TILE_M, 512, SMEM_TOTAL>>>(z);
    vq_finalize_kernel<<<nrows / 8, 256>>>(z, emb, out, nrows);
    vq_reduce1_kernel<<<64, 256>>>(nrows / 8);
    vq_reduce2_kernel<<<1, 64>>>(out, 1.0 / ((double)nrows * EDIM),
                                 (size_t)nrows * EDIM);
}